// round 14
// baseline (speedup 1.0000x reference)
#include <cuda_runtime.h>
#include <cuda_bf16.h>

// Problem dims
#define HB    1024
#define NH    16
#define HD    64
#define SEQ   2048
#define BATCH 2
#define ROWS  (BATCH*SEQ)     // 4096
#define EPS   1e-12f
#define W2    (HB/2)          // 512 packed u32 per hidden row
#define LOG2E 1.4426950408889634f

// -------------------- scratch (device globals; no runtime allocs) -----------
__device__ unsigned g_xnb [ROWS*W2];     // layernorm output, bf16 packed
__device__ unsigned g_wb  [4*HB*W2];     // wq,wk,wv,wo bf16 packed [mat][n][k2]
__device__ unsigned g_qb  [ROWS*W2];     // [B,NH,S,HD/2]
__device__ unsigned g_kb  [ROWS*W2];
__device__ unsigned g_vb  [ROWS*W2];
__device__ unsigned g_ctxb[ROWS*W2];     // [B,S,H/2]

// -------------------- bf16 helpers ------------------------------------------
__device__ __forceinline__ unsigned pack2(float a, float b) {
    unsigned r;
    asm("{ .reg .b16 lo, hi;\n\t"
        "cvt.rn.bf16.f32 lo, %1;\n\t"
        "cvt.rn.bf16.f32 hi, %2;\n\t"
        "mov.b32 %0, {lo, hi}; }"
        : "=r"(r) : "f"(a), "f"(b));
    return r;
}
// D += A(16x16) * B(16x8), bf16 in, f32 accum.
__device__ __forceinline__ void mma_bf16(float* d, const unsigned* a, const unsigned* b) {
    asm volatile(
        "mma.sync.aligned.m16n8k16.row.col.f32.bf16.bf16.f32 "
        "{%0,%1,%2,%3}, {%4,%5,%6,%7}, {%8,%9}, {%0,%1,%2,%3};"
        : "+f"(d[0]), "+f"(d[1]), "+f"(d[2]), "+f"(d[3])
        : "r"(a[0]), "r"(a[1]), "r"(a[2]), "r"(a[3]), "r"(b[0]), "r"(b[1]));
}

// ============================ LayerNorm (writes bf16 planes) ================
__global__ __launch_bounds__(256) void ln_kernel(
    const float* __restrict__ x,
    const float* __restrict__ gamma,
    const float* __restrict__ beta)
{
    int row = blockIdx.x;
    const float* xr = x + (size_t)row * HB;
    int tid = threadIdx.x;

    float4 v = *(const float4*)(xr + tid * 4);
    float s  = v.x + v.y + v.z + v.w;
    float ss = v.x*v.x + v.y*v.y + v.z*v.z + v.w*v.w;

    #pragma unroll
    for (int o = 16; o; o >>= 1) {
        s  += __shfl_xor_sync(0xffffffffu, s,  o);
        ss += __shfl_xor_sync(0xffffffffu, ss, o);
    }
    __shared__ float sh_s[8], sh_ss[8];
    int wid = tid >> 5, lid = tid & 31;
    if (lid == 0) { sh_s[wid] = s; sh_ss[wid] = ss; }
    __syncthreads();
    if (wid == 0) {
        float a = (lid < 8) ? sh_s[lid]  : 0.f;
        float b = (lid < 8) ? sh_ss[lid] : 0.f;
        #pragma unroll
        for (int o = 4; o; o >>= 1) {
            a += __shfl_xor_sync(0xffffffffu, a, o);
            b += __shfl_xor_sync(0xffffffffu, b, o);
        }
        if (lid == 0) { sh_s[0] = a; sh_ss[0] = b; }
    }
    __syncthreads();
    float mean = sh_s[0] * (1.0f / HB);
    float var  = sh_ss[0] * (1.0f / HB) - mean * mean;
    float rstd = rsqrtf(var + EPS);

    float4 g  = *(const float4*)(gamma + tid * 4);
    float4 be = *(const float4*)(beta + tid * 4);
    float o0 = (v.x - mean) * rstd * g.x + be.x;
    float o1 = (v.y - mean) * rstd * g.y + be.y;
    float o2 = (v.z - mean) * rstd * g.z + be.z;
    float o3 = (v.w - mean) * rstd * g.w + be.w;
    *(uint2*)(g_xnb + (size_t)row * W2 + tid * 2) =
        make_uint2(pack2(o0, o1), pack2(o2, o3));
}

// ============================ Weight conversion =============================
__global__ __launch_bounds__(256) void conv_w(
    const float* __restrict__ wq, const float* __restrict__ wk,
    const float* __restrict__ wv, const float* __restrict__ wo)
{
    int gid = blockIdx.x * 256 + threadIdx.x;
    int mat = gid >> 18;
    int off = gid & 262143;
    const float* src = (mat == 0 ? wq : mat == 1 ? wk : mat == 2 ? wv : wo)
                       + (size_t)off * 4;
    float4 v = *(const float4*)src;
    *(uint2*)(g_wb + (size_t)mat * HB * W2 + (size_t)off * 2) =
        make_uint2(pack2(v.x, v.y), pack2(v.z, v.w));
}

// ====================== bf16 GEMM mainloop (double-buffered) ================
#define PL_S  136
#define STG   (16*PL_S)
#define STAGE2 (2*STG)

__device__ __forceinline__ void gemm_mainloop(
    const unsigned* __restrict__ Ag,
    const unsigned* __restrict__ Bg,
    unsigned* Sh,
    float (*acc)[4][4])
{
    int tid  = threadIdx.x;
    int side = tid >> 7;
    int row  = tid & 127;
    int lane = tid & 31, w = tid >> 5;
    int t4 = lane >> 2, q = lane & 3;
    int wm = (w >> 2) * 64, wn = (w & 3) * 32;

    const unsigned* grow = (side ? Bg : Ag) + (size_t)row * W2;

    uint4 r0 = *(const uint4*)(grow     );
    uint4 r1 = *(const uint4*)(grow +  4);
    uint4 r2 = *(const uint4*)(grow +  8);
    uint4 r3 = *(const uint4*)(grow + 12);
    {
        unsigned* stb = Sh + side * STG + row;
        stb[ 0*PL_S]=r0.x; stb[ 1*PL_S]=r0.y; stb[ 2*PL_S]=r0.z; stb[ 3*PL_S]=r0.w;
        stb[ 4*PL_S]=r1.x; stb[ 5*PL_S]=r1.y; stb[ 6*PL_S]=r1.z; stb[ 7*PL_S]=r1.w;
        stb[ 8*PL_S]=r2.x; stb[ 9*PL_S]=r2.y; stb[10*PL_S]=r2.z; stb[11*PL_S]=r2.w;
        stb[12*PL_S]=r3.x; stb[13*PL_S]=r3.y; stb[14*PL_S]=r3.z; stb[15*PL_S]=r3.w;
    }
    __syncthreads();

    int cur = 0;
    for (int k0 = 32; k0 <= HB; k0 += 32) {
        if (k0 < HB) {
            const unsigned* g2 = grow + (k0 >> 1);
            r0 = *(const uint4*)(g2     );
            r1 = *(const uint4*)(g2 +  4);
            r2 = *(const uint4*)(g2 +  8);
            r3 = *(const uint4*)(g2 + 12);
        }
        const unsigned* Ahs = Sh + cur * STAGE2;
        const unsigned* Bhs = Ahs + STG;
        #pragma unroll
        for (int s = 0; s < 2; s++) {
            int kb = s * 8;
            unsigned ah[4][4], bh[4][2];
            #pragma unroll
            for (int mt = 0; mt < 4; mt++) {
                int r = wm + mt*16 + t4;
                ah[mt][0] = Ahs[(kb+q  )*PL_S + r    ];
                ah[mt][1] = Ahs[(kb+q  )*PL_S + r + 8];
                ah[mt][2] = Ahs[(kb+q+4)*PL_S + r    ];
                ah[mt][3] = Ahs[(kb+q+4)*PL_S + r + 8];
            }
            #pragma unroll
            for (int nt = 0; nt < 4; nt++) {
                int c = wn + nt*8 + t4;
                bh[nt][0] = Bhs[(kb+q  )*PL_S + c];
                bh[nt][1] = Bhs[(kb+q+4)*PL_S + c];
            }
            #pragma unroll
            for (int mt = 0; mt < 4; mt++)
                #pragma unroll
                for (int nt = 0; nt < 4; nt++)
                    mma_bf16(acc[mt][nt], ah[mt], bh[nt]);
        }
        if (k0 < HB) {
            unsigned* stb = Sh + (cur^1) * STAGE2 + side * STG + row;
            stb[ 0*PL_S]=r0.x; stb[ 1*PL_S]=r0.y; stb[ 2*PL_S]=r0.z; stb[ 3*PL_S]=r0.w;
            stb[ 4*PL_S]=r1.x; stb[ 5*PL_S]=r1.y; stb[ 6*PL_S]=r1.z; stb[ 7*PL_S]=r1.w;
            stb[ 8*PL_S]=r2.x; stb[ 9*PL_S]=r2.y; stb[10*PL_S]=r2.z; stb[11*PL_S]=r2.w;
            stb[12*PL_S]=r3.x; stb[13*PL_S]=r3.y; stb[14*PL_S]=r3.z; stb[15*PL_S]=r3.w;
        }
        __syncthreads();
        cur ^= 1;
    }
}

// ---- QKV projections: write packed bf16, scattered to [B,NH,S,HD/2] --------
__global__ __launch_bounds__(256) void qkv_gemm_t(
    const float* __restrict__ bq, const float* __restrict__ bk,
    const float* __restrict__ bv)
{
    int z = blockIdx.z;
    const float* bias = (z == 0) ? bq : (z == 1) ? bk : bv;
    unsigned* O = (z == 0) ? g_qb : (z == 1) ? g_kb : g_vb;

    __shared__ __align__(16) unsigned Sh[2*STAGE2];

    const unsigned* Ag = g_xnb + (size_t)(blockIdx.y * 128) * W2;
    const unsigned* Bg = g_wb + (size_t)z * HB * W2 + (size_t)(blockIdx.x * 128) * W2;

    float acc[4][4][4];
    #pragma unroll
    for (int mt = 0; mt < 4; mt++)
        #pragma unroll
        for (int nt = 0; nt < 4; nt++)
            acc[mt][nt][0] = acc[mt][nt][1] = acc[mt][nt][2] = acc[mt][nt][3] = 0.f;

    gemm_mainloop(Ag, Bg, Sh, acc);

    int tid = threadIdx.x;
    int lane = tid & 31, w = tid >> 5;
    int t4 = lane >> 2, q = lane & 3;
    int wm = (w >> 2) * 64, wn = (w & 3) * 32;

    #pragma unroll
    for (int nt = 0; nt < 4; nt++) {
        int col = blockIdx.x * 128 + wn + nt*8 + 2*q;
        int h   = col >> 6;
        int dp  = (col & 63) >> 1;
        float b0 = bias[col], b1 = bias[col + 1];
        #pragma unroll
        for (int mt = 0; mt < 4; mt++) {
            int m  = blockIdx.y * 128 + wm + mt*16 + t4;
            int b_ = m >> 11;
            int s_ = m & 2047;
            unsigned* dst = O + ((size_t)(b_ * NH + h) * SEQ + s_) * (HD/2) + dp;
            dst[0]          = pack2(acc[mt][nt][0] + b0, acc[mt][nt][1] + b1);
            dst[8 * (HD/2)] = pack2(acc[mt][nt][2] + b0, acc[mt][nt][3] + b1);
        }
    }
}

// ---- Output projection + residual (f32 out) --------------------------------
__global__ __launch_bounds__(256) void out_gemm_t(
    const float* __restrict__ bo,
    const float* __restrict__ hs, float* __restrict__ out)
{
    __shared__ __align__(16) unsigned Sh[2*STAGE2];

    const unsigned* Ag = g_ctxb + (size_t)(blockIdx.y * 128) * W2;
    const unsigned* Bg = g_wb + (size_t)3 * HB * W2 + (size_t)(blockIdx.x * 128) * W2;

    float acc[4][4][4];
    #pragma unroll
    for (int mt = 0; mt < 4; mt++)
        #pragma unroll
        for (int nt = 0; nt < 4; nt++)
            acc[mt][nt][0] = acc[mt][nt][1] = acc[mt][nt][2] = acc[mt][nt][3] = 0.f;

    gemm_mainloop(Ag, Bg, Sh, acc);

    int tid = threadIdx.x;
    int lane = tid & 31, w = tid >> 5;
    int t4 = lane >> 2, q = lane & 3;
    int wm = (w >> 2) * 64, wn = (w & 3) * 32;

    #pragma unroll
    for (int nt = 0; nt < 4; nt++) {
        int col = blockIdx.x * 128 + wn + nt*8 + 2*q;
        float b0 = bo[col], b1 = bo[col + 1];
        #pragma unroll
        for (int mt = 0; mt < 4; mt++) {
            int m = blockIdx.y * 128 + wm + mt*16 + t4;
            const float* hr = hs + (size_t)m * HB + col;
            float* dst = out + (size_t)m * HB + col;
            float2 r0 = *(const float2*)hr;
            *(float2*)dst = make_float2(acc[mt][nt][0] + b0 + r0.x,
                                        acc[mt][nt][1] + b1 + r0.y);
            const float* hr2 = hr + 8 * HB;
            float* dst2 = dst + 8 * HB;
            float2 r1 = *(const float2*)hr2;
            *(float2*)dst2 = make_float2(acc[mt][nt][2] + b0 + r1.x,
                                         acc[mt][nt][3] + b1 + r1.y);
        }
    }
}

// ============================ Flash attention (bf16, occupancy-tuned) =======
// 128 threads / 4 warps per CTA, 64 queries per CTA (warp w: rows [w*16,w*16+16)).
// 3 CTAs/SM target. Double-buffered K/V staging, base-2 softmax.
#define KS_S 36   // u32 stride, Ks rows = keys, cols = dim-pairs
#define VS_S 72   // u32 stride, Vs rows = key-pairs, cols = dims
#define SC2  (0.125f * LOG2E)

__global__ __launch_bounds__(128, 3) void attn_t(const float* __restrict__ mask)
{
    __shared__ __align__(16) unsigned Ks[2][64 * KS_S];
    __shared__ __align__(16) unsigned Vs[2][32 * VS_S];
    __shared__ float Ms[2][64];

    int tid  = threadIdx.x;
    int w    = tid >> 5;
    int lane = tid & 31;
    int t4   = lane >> 2;
    int q    = lane & 3;

    int bh = blockIdx.y;
    int b  = bh >> 4;
    int h  = bh & 15;
    int q0 = blockIdx.x * 64;

    const unsigned* Qp = g_qb + (size_t)bh * SEQ * (HD/2) + (size_t)(q0 + w * 16) * (HD/2);
    const unsigned* Kp = g_kb + (size_t)bh * SEQ * (HD/2);
    const unsigned* Vp = g_vb + (size_t)bh * SEQ * (HD/2);
    const float* mrow  = mask + (size_t)b * SEQ;

    // Q A-fragments (already packed dim-pairs)
    unsigned aq[4][4];
    #pragma unroll
    for (int c = 0; c < 4; c++) {
        aq[c][0] = Qp[(size_t)(t4    ) * (HD/2) + c*8 + q    ];
        aq[c][1] = Qp[(size_t)(t4 + 8) * (HD/2) + c*8 + q    ];
        aq[c][2] = Qp[(size_t)(t4    ) * (HD/2) + c*8 + q + 4];
        aq[c][3] = Qp[(size_t)(t4 + 8) * (HD/2) + c*8 + q + 4];
    }

    // staging assignments (128 threads)
    int kr  = tid & 63;            // K: key row
    int kc0 = (tid >> 6) * 4;      // K: first of 4 uint4 chunks (0 or 4)
    int vk  = tid >> 2;            // V: key-pair row (0..31)
    int vj0 = (tid & 3) * 2;       // V: first of 2 chunks (each 4 u32)

    uint4 kreg[4], va[2], vb[2];
    float mreg = 0.f;

    auto LOADT = [&](int kt0) {
        const unsigned* krow = Kp + (size_t)(kt0 + kr) * 32;
        #pragma unroll
        for (int i = 0; i < 4; i++)
            kreg[i] = *(const uint4*)(krow + (kc0 + i) * 4);
        #pragma unroll
        for (int i = 0; i < 2; i++) {
            va[i] = *(const uint4*)(Vp + (size_t)(kt0 + 2*vk    ) * 32 + (vj0 + i) * 4);
            vb[i] = *(const uint4*)(Vp + (size_t)(kt0 + 2*vk + 1) * 32 + (vj0 + i) * 4);
        }
        if (tid < 64) mreg = mrow[kt0 + tid] * LOG2E;
    };
    auto STORET = [&](int st) {
        #pragma unroll
        for (int i = 0; i < 4; i++)
            *(uint4*)&Ks[st][kr * KS_S + (kc0 + i) * 4] = kreg[i];
        #pragma unroll
        for (int i = 0; i < 2; i++) {
            uint4 o0;
            o0.x = __byte_perm(va[i].x, vb[i].x, 0x5410);
            o0.y = __byte_perm(va[i].x, vb[i].x, 0x7632);
            o0.z = __byte_perm(va[i].y, vb[i].y, 0x5410);
            o0.w = __byte_perm(va[i].y, vb[i].y, 0x7632);
            uint4 o1;
            o1.x = __byte_perm(va[i].z, vb[i].z, 0x5410);
            o1.y = __byte_perm(va[i].z, vb[i].z, 0x7632);
            o1.z = __byte_perm(va[i].w, vb[i].w, 0x5410);
            o1.w = __byte_perm(va[i].w, vb[i].w, 0x7632);
            *(uint4*)&Vs[st][vk * VS_S + (vj0 + i) * 8    ] = o0;
            *(uint4*)&Vs[st][vk * VS_S + (vj0 + i) * 8 + 4] = o1;
        }
        if (tid < 64) Ms[st][tid] = mreg;
    };

    float mA = -1e30f, mB = -1e30f, lA = 0.f, lB = 0.f;
    float o[8][4];
    #pragma unroll
    for (int nt = 0; nt < 8; nt++)
        o[nt][0] = o[nt][1] = o[nt][2] = o[nt][3] = 0.f;

    LOADT(0);
    STORET(0);
    __syncthreads();

    int cur = 0;
    for (int t = 0; t < SEQ/64; t++) {
        if (t + 1 < SEQ/64) LOADT((t + 1) * 64);

        const unsigned* Kss = Ks[cur];
        const unsigned* Vss = Vs[cur];
        const float*    Mss = Ms[cur];

        // ---- QK^T ----
        float s[8][4];
        #pragma unroll
        for (int nt = 0; nt < 8; nt++)
            s[nt][0] = s[nt][1] = s[nt][2] = s[nt][3] = 0.f;

        #pragma unroll
        for (int c = 0; c < 4; c++) {
            #pragma unroll
            for (int nt = 0; nt < 8; nt++) {
                unsigned bb[2];
                bb[0] = Kss[(nt*8 + t4) * KS_S + c*8 + q    ];
                bb[1] = Kss[(nt*8 + t4) * KS_S + c*8 + 4 + q];
                mma_bf16(s[nt], aq[c], bb);
            }
        }

        // ---- scale + mask (base-2 domain) ----
        #pragma unroll
        for (int nt = 0; nt < 8; nt++) {
            float mk0 = Mss[nt*8 + 2*q];
            float mk1 = Mss[nt*8 + 2*q + 1];
            s[nt][0] = s[nt][0] * SC2 + mk0;
            s[nt][1] = s[nt][1] * SC2 + mk1;
            s[nt][2] = s[nt][2] * SC2 + mk0;
            s[nt][3] = s[nt][3] * SC2 + mk1;
        }

        // ---- online softmax, base 2 (rows rA=t4, rB=t4+8; quad reduce) ----
        float mxA = -1e30f, mxB = -1e30f;
        #pragma unroll
        for (int nt = 0; nt < 8; nt++) {
            mxA = fmaxf(mxA, fmaxf(s[nt][0], s[nt][1]));
            mxB = fmaxf(mxB, fmaxf(s[nt][2], s[nt][3]));
        }
        mxA = fmaxf(mxA, __shfl_xor_sync(0xffffffffu, mxA, 1));
        mxA = fmaxf(mxA, __shfl_xor_sync(0xffffffffu, mxA, 2));
        mxB = fmaxf(mxB, __shfl_xor_sync(0xffffffffu, mxB, 1));
        mxB = fmaxf(mxB, __shfl_xor_sync(0xffffffffu, mxB, 2));
        float mAn = fmaxf(mA, mxA), mBn = fmaxf(mB, mxB);
        float alA = exp2f(mA - mAn), alB = exp2f(mB - mBn);
        float sumA = 0.f, sumB = 0.f;
        #pragma unroll
        for (int nt = 0; nt < 8; nt++) {
            s[nt][0] = exp2f(s[nt][0] - mAn);
            s[nt][1] = exp2f(s[nt][1] - mAn);
            s[nt][2] = exp2f(s[nt][2] - mBn);
            s[nt][3] = exp2f(s[nt][3] - mBn);
            sumA += s[nt][0] + s[nt][1];
            sumB += s[nt][2] + s[nt][3];
        }
        sumA += __shfl_xor_sync(0xffffffffu, sumA, 1);
        sumA += __shfl_xor_sync(0xffffffffu, sumA, 2);
        sumB += __shfl_xor_sync(0xffffffffu, sumB, 1);
        sumB += __shfl_xor_sync(0xffffffffu, sumB, 2);
        lA = lA * alA + sumA;  mA = mAn;
        lB = lB * alB + sumB;  mB = mBn;
        #pragma unroll
        for (int nt = 0; nt < 8; nt++) {
            o[nt][0] *= alA; o[nt][1] *= alA;
            o[nt][2] *= alB; o[nt][3] *= alB;
        }

        // ---- PV: P D-fragments repack directly into A-fragments ----
        #pragma unroll
        for (int pk = 0; pk < 4; pk++) {
            unsigned pa[4];
            pa[0] = pack2(s[2*pk  ][0], s[2*pk  ][1]);
            pa[1] = pack2(s[2*pk  ][2], s[2*pk  ][3]);
            pa[2] = pack2(s[2*pk+1][0], s[2*pk+1][1]);
            pa[3] = pack2(s[2*pk+1][2], s[2*pk+1][3]);
            #pragma unroll
            for (int nt = 0; nt < 8; nt++) {
                unsigned bb[2];
                bb[0] = Vss[(pk*8 + q    ) * VS_S + nt*8 + t4];
                bb[1] = Vss[(pk*8 + q + 4) * VS_S + nt*8 + t4];
                mma_bf16(o[nt], pa, bb);
            }
        }

        if (t + 1 < SEQ/64) STORET(cur ^ 1);
        __syncthreads();
        cur ^= 1;
    }

    // ---- epilogue -> g_ctxb packed [B,S,H/2] ----
    float invA = 1.0f / lA, invB = 1.0f / lB;
    int srowA = q0 + w * 16 + t4;
    unsigned* crow  = g_ctxb + (size_t)(b * SEQ + srowA    ) * W2 + h * 32;
    unsigned* crow2 = g_ctxb + (size_t)(b * SEQ + srowA + 8) * W2 + h * 32;
    #pragma unroll
    for (int nt = 0; nt < 8; nt++) {
        crow [nt*4 + q] = pack2(o[nt][0] * invA, o[nt][1] * invA);
        crow2[nt*4 + q] = pack2(o[nt][2] * invB, o[nt][3] * invB);
    }
}

// ============================ launch ========================================
extern "C" void kernel_launch(void* const* d_in, const int* in_sizes, int n_in,
                              void* d_out, int out_size)
{
    const float* hs    = (const float*)d_in[0];
    const float* mask  = (const float*)d_in[1];
    const float* wq    = (const float*)d_in[2];
    const float* bq    = (const float*)d_in[3];
    const float* wk    = (const float*)d_in[4];
    const float* bk    = (const float*)d_in[5];
    const float* wv    = (const float*)d_in[6];
    const float* bv    = (const float*)d_in[7];
    const float* wo    = (const float*)d_in[8];
    const float* bo    = (const float*)d_in[9];
    const float* gamma = (const float*)d_in[10];
    const float* beta  = (const float*)d_in[11];
    float* out = (float*)d_out;

    conv_w<<<4096, 256>>>(wq, wk, wv, wo);
    ln_kernel<<<ROWS, 256>>>(hs, gamma, beta);
    qkv_gemm_t<<<dim3(HB/128, ROWS/128, 3), 256>>>(bq, bk, bv);
    attn_t<<<dim3(SEQ/64, BATCH*NH), 128>>>(mask);
    out_gemm_t<<<dim3(HB/128, ROWS/128), 256>>>(bo, hs, out);
}

// round 15
// speedup vs baseline: 1.6923x; 1.6923x over previous
#include <cuda_runtime.h>
#include <cuda_bf16.h>

// Problem dims
#define HB    1024
#define NH    16
#define HD    64
#define SEQ   2048
#define BATCH 2
#define ROWS  (BATCH*SEQ)     // 4096
#define EPS   1e-12f
#define W2    (HB/2)          // 512 packed u32 per hidden row
#define LOG2E 1.4426950408889634f

// -------------------- scratch (device globals; no runtime allocs) -----------
__device__ unsigned g_xnb [ROWS*W2];     // layernorm output, bf16 packed
__device__ unsigned g_wb  [4*HB*W2];     // wq,wk,wv,wo bf16 packed [mat][n][k2]
__device__ unsigned g_qb  [ROWS*W2];     // [B,NH,S,HD/2]
__device__ unsigned g_kb  [ROWS*W2];
__device__ unsigned g_vb  [ROWS*W2];
__device__ unsigned g_ctxb[ROWS*W2];     // [B,S,H/2]

// -------------------- bf16 helpers ------------------------------------------
__device__ __forceinline__ unsigned pack2(float a, float b) {
    unsigned r;
    asm("{ .reg .b16 lo, hi;\n\t"
        "cvt.rn.bf16.f32 lo, %1;\n\t"
        "cvt.rn.bf16.f32 hi, %2;\n\t"
        "mov.b32 %0, {lo, hi}; }"
        : "=r"(r) : "f"(a), "f"(b));
    return r;
}
// D += A(16x16) * B(16x8), bf16 in, f32 accum.
__device__ __forceinline__ void mma_bf16(float* d, const unsigned* a, const unsigned* b) {
    asm volatile(
        "mma.sync.aligned.m16n8k16.row.col.f32.bf16.bf16.f32 "
        "{%0,%1,%2,%3}, {%4,%5,%6,%7}, {%8,%9}, {%0,%1,%2,%3};"
        : "+f"(d[0]), "+f"(d[1]), "+f"(d[2]), "+f"(d[3])
        : "r"(a[0]), "r"(a[1]), "r"(a[2]), "r"(a[3]), "r"(b[0]), "r"(b[1]));
}
// cp.async 16B gmem -> smem
__device__ __forceinline__ void cp16(unsigned* smem_dst, const void* gsrc) {
    unsigned d = (unsigned)__cvta_generic_to_shared(smem_dst);
    asm volatile("cp.async.cg.shared.global [%0], [%1], 16;" :: "r"(d), "l"(gsrc));
}
__device__ __forceinline__ void cp_commit() {
    asm volatile("cp.async.commit_group;");
}
__device__ __forceinline__ void cp_wait0() {
    asm volatile("cp.async.wait_group 0;");
}

// ============================ LayerNorm (writes bf16 planes) ================
__global__ __launch_bounds__(256) void ln_kernel(
    const float* __restrict__ x,
    const float* __restrict__ gamma,
    const float* __restrict__ beta)
{
    int row = blockIdx.x;
    const float* xr = x + (size_t)row * HB;
    int tid = threadIdx.x;

    float4 v = *(const float4*)(xr + tid * 4);
    float s  = v.x + v.y + v.z + v.w;
    float ss = v.x*v.x + v.y*v.y + v.z*v.z + v.w*v.w;

    #pragma unroll
    for (int o = 16; o; o >>= 1) {
        s  += __shfl_xor_sync(0xffffffffu, s,  o);
        ss += __shfl_xor_sync(0xffffffffu, ss, o);
    }
    __shared__ float sh_s[8], sh_ss[8];
    int wid = tid >> 5, lid = tid & 31;
    if (lid == 0) { sh_s[wid] = s; sh_ss[wid] = ss; }
    __syncthreads();
    if (wid == 0) {
        float a = (lid < 8) ? sh_s[lid]  : 0.f;
        float b = (lid < 8) ? sh_ss[lid] : 0.f;
        #pragma unroll
        for (int o = 4; o; o >>= 1) {
            a += __shfl_xor_sync(0xffffffffu, a, o);
            b += __shfl_xor_sync(0xffffffffu, b, o);
        }
        if (lid == 0) { sh_s[0] = a; sh_ss[0] = b; }
    }
    __syncthreads();
    float mean = sh_s[0] * (1.0f / HB);
    float var  = sh_ss[0] * (1.0f / HB) - mean * mean;
    float rstd = rsqrtf(var + EPS);

    float4 g  = *(const float4*)(gamma + tid * 4);
    float4 be = *(const float4*)(beta + tid * 4);
    float o0 = (v.x - mean) * rstd * g.x + be.x;
    float o1 = (v.y - mean) * rstd * g.y + be.y;
    float o2 = (v.z - mean) * rstd * g.z + be.z;
    float o3 = (v.w - mean) * rstd * g.w + be.w;
    *(uint2*)(g_xnb + (size_t)row * W2 + tid * 2) =
        make_uint2(pack2(o0, o1), pack2(o2, o3));
}

// ============================ Weight conversion =============================
__global__ __launch_bounds__(256) void conv_w(
    const float* __restrict__ wq, const float* __restrict__ wk,
    const float* __restrict__ wv, const float* __restrict__ wo)
{
    int gid = blockIdx.x * 256 + threadIdx.x;
    int mat = gid >> 18;
    int off = gid & 262143;
    const float* src = (mat == 0 ? wq : mat == 1 ? wk : mat == 2 ? wv : wo)
                       + (size_t)off * 4;
    float4 v = *(const float4*)src;
    *(uint2*)(g_wb + (size_t)mat * HB * W2 + (size_t)off * 2) =
        make_uint2(pack2(v.x, v.y), pack2(v.z, v.w));
}

// ====================== bf16 GEMM mainloop (double-buffered) ================
#define PL_S  136
#define STG   (16*PL_S)
#define STAGE2 (2*STG)

__device__ __forceinline__ void gemm_mainloop(
    const unsigned* __restrict__ Ag,
    const unsigned* __restrict__ Bg,
    unsigned* Sh,
    float (*acc)[4][4])
{
    int tid  = threadIdx.x;
    int side = tid >> 7;
    int row  = tid & 127;
    int lane = tid & 31, w = tid >> 5;
    int t4 = lane >> 2, q = lane & 3;
    int wm = (w >> 2) * 64, wn = (w & 3) * 32;

    const unsigned* grow = (side ? Bg : Ag) + (size_t)row * W2;

    uint4 r0 = *(const uint4*)(grow     );
    uint4 r1 = *(const uint4*)(grow +  4);
    uint4 r2 = *(const uint4*)(grow +  8);
    uint4 r3 = *(const uint4*)(grow + 12);
    {
        unsigned* stb = Sh + side * STG + row;
        stb[ 0*PL_S]=r0.x; stb[ 1*PL_S]=r0.y; stb[ 2*PL_S]=r0.z; stb[ 3*PL_S]=r0.w;
        stb[ 4*PL_S]=r1.x; stb[ 5*PL_S]=r1.y; stb[ 6*PL_S]=r1.z; stb[ 7*PL_S]=r1.w;
        stb[ 8*PL_S]=r2.x; stb[ 9*PL_S]=r2.y; stb[10*PL_S]=r2.z; stb[11*PL_S]=r2.w;
        stb[12*PL_S]=r3.x; stb[13*PL_S]=r3.y; stb[14*PL_S]=r3.z; stb[15*PL_S]=r3.w;
    }
    __syncthreads();

    int cur = 0;
    for (int k0 = 32; k0 <= HB; k0 += 32) {
        if (k0 < HB) {
            const unsigned* g2 = grow + (k0 >> 1);
            r0 = *(const uint4*)(g2     );
            r1 = *(const uint4*)(g2 +  4);
            r2 = *(const uint4*)(g2 +  8);
            r3 = *(const uint4*)(g2 + 12);
        }
        const unsigned* Ahs = Sh + cur * STAGE2;
        const unsigned* Bhs = Ahs + STG;
        #pragma unroll
        for (int s = 0; s < 2; s++) {
            int kb = s * 8;
            unsigned ah[4][4], bh[4][2];
            #pragma unroll
            for (int mt = 0; mt < 4; mt++) {
                int r = wm + mt*16 + t4;
                ah[mt][0] = Ahs[(kb+q  )*PL_S + r    ];
                ah[mt][1] = Ahs[(kb+q  )*PL_S + r + 8];
                ah[mt][2] = Ahs[(kb+q+4)*PL_S + r    ];
                ah[mt][3] = Ahs[(kb+q+4)*PL_S + r + 8];
            }
            #pragma unroll
            for (int nt = 0; nt < 4; nt++) {
                int c = wn + nt*8 + t4;
                bh[nt][0] = Bhs[(kb+q  )*PL_S + c];
                bh[nt][1] = Bhs[(kb+q+4)*PL_S + c];
            }
            #pragma unroll
            for (int mt = 0; mt < 4; mt++)
                #pragma unroll
                for (int nt = 0; nt < 4; nt++)
                    mma_bf16(acc[mt][nt], ah[mt], bh[nt]);
        }
        if (k0 < HB) {
            unsigned* stb = Sh + (cur^1) * STAGE2 + side * STG + row;
            stb[ 0*PL_S]=r0.x; stb[ 1*PL_S]=r0.y; stb[ 2*PL_S]=r0.z; stb[ 3*PL_S]=r0.w;
            stb[ 4*PL_S]=r1.x; stb[ 5*PL_S]=r1.y; stb[ 6*PL_S]=r1.z; stb[ 7*PL_S]=r1.w;
            stb[ 8*PL_S]=r2.x; stb[ 9*PL_S]=r2.y; stb[10*PL_S]=r2.z; stb[11*PL_S]=r2.w;
            stb[12*PL_S]=r3.x; stb[13*PL_S]=r3.y; stb[14*PL_S]=r3.z; stb[15*PL_S]=r3.w;
        }
        __syncthreads();
        cur ^= 1;
    }
}

// ---- QKV projections: write packed bf16, scattered to [B,NH,S,HD/2] --------
__global__ __launch_bounds__(256) void qkv_gemm_t(
    const float* __restrict__ bq, const float* __restrict__ bk,
    const float* __restrict__ bv)
{
    int z = blockIdx.z;
    const float* bias = (z == 0) ? bq : (z == 1) ? bk : bv;
    unsigned* O = (z == 0) ? g_qb : (z == 1) ? g_kb : g_vb;

    __shared__ __align__(16) unsigned Sh[2*STAGE2];

    const unsigned* Ag = g_xnb + (size_t)(blockIdx.y * 128) * W2;
    const unsigned* Bg = g_wb + (size_t)z * HB * W2 + (size_t)(blockIdx.x * 128) * W2;

    float acc[4][4][4];
    #pragma unroll
    for (int mt = 0; mt < 4; mt++)
        #pragma unroll
        for (int nt = 0; nt < 4; nt++)
            acc[mt][nt][0] = acc[mt][nt][1] = acc[mt][nt][2] = acc[mt][nt][3] = 0.f;

    gemm_mainloop(Ag, Bg, Sh, acc);

    int tid = threadIdx.x;
    int lane = tid & 31, w = tid >> 5;
    int t4 = lane >> 2, q = lane & 3;
    int wm = (w >> 2) * 64, wn = (w & 3) * 32;

    #pragma unroll
    for (int nt = 0; nt < 4; nt++) {
        int col = blockIdx.x * 128 + wn + nt*8 + 2*q;
        int h   = col >> 6;
        int dp  = (col & 63) >> 1;
        float b0 = bias[col], b1 = bias[col + 1];
        #pragma unroll
        for (int mt = 0; mt < 4; mt++) {
            int m  = blockIdx.y * 128 + wm + mt*16 + t4;
            int b_ = m >> 11;
            int s_ = m & 2047;
            unsigned* dst = O + ((size_t)(b_ * NH + h) * SEQ + s_) * (HD/2) + dp;
            dst[0]          = pack2(acc[mt][nt][0] + b0, acc[mt][nt][1] + b1);
            dst[8 * (HD/2)] = pack2(acc[mt][nt][2] + b0, acc[mt][nt][3] + b1);
        }
    }
}

// ---- Output projection + residual (f32 out) --------------------------------
__global__ __launch_bounds__(256) void out_gemm_t(
    const float* __restrict__ bo,
    const float* __restrict__ hs, float* __restrict__ out)
{
    __shared__ __align__(16) unsigned Sh[2*STAGE2];

    const unsigned* Ag = g_ctxb + (size_t)(blockIdx.y * 128) * W2;
    const unsigned* Bg = g_wb + (size_t)3 * HB * W2 + (size_t)(blockIdx.x * 128) * W2;

    float acc[4][4][4];
    #pragma unroll
    for (int mt = 0; mt < 4; mt++)
        #pragma unroll
        for (int nt = 0; nt < 4; nt++)
            acc[mt][nt][0] = acc[mt][nt][1] = acc[mt][nt][2] = acc[mt][nt][3] = 0.f;

    gemm_mainloop(Ag, Bg, Sh, acc);

    int tid = threadIdx.x;
    int lane = tid & 31, w = tid >> 5;
    int t4 = lane >> 2, q = lane & 3;
    int wm = (w >> 2) * 64, wn = (w & 3) * 32;

    #pragma unroll
    for (int nt = 0; nt < 4; nt++) {
        int col = blockIdx.x * 128 + wn + nt*8 + 2*q;
        float b0 = bo[col], b1 = bo[col + 1];
        #pragma unroll
        for (int mt = 0; mt < 4; mt++) {
            int m = blockIdx.y * 128 + wm + mt*16 + t4;
            const float* hr = hs + (size_t)m * HB + col;
            float* dst = out + (size_t)m * HB + col;
            float2 r0 = *(const float2*)hr;
            *(float2*)dst = make_float2(acc[mt][nt][0] + b0 + r0.x,
                                        acc[mt][nt][1] + b1 + r0.y);
            const float* hr2 = hr + 8 * HB;
            float* dst2 = dst + 8 * HB;
            float2 r1 = *(const float2*)hr2;
            *(float2*)dst2 = make_float2(acc[mt][nt][2] + b0 + r1.x,
                                         acc[mt][nt][3] + b1 + r1.y);
        }
    }
}

// ============================ Flash attention ===============================
// 256 threads / 8 warps, 128 queries per CTA (R11 shape), 2 CTAs/SM target.
// K staged by cp.async (zero regs); V staged via regs + byte_perm repack.
// Double-buffered, base-2 softmax.
#define KS_S 36   // u32 stride, Ks rows = keys, cols = dim-pairs
#define VS_S 72   // u32 stride, Vs rows = key-pairs, cols = dims
#define SC2  (0.125f * LOG2E)

__global__ __launch_bounds__(256, 2) void attn_t(const float* __restrict__ mask)
{
    __shared__ __align__(16) unsigned Ks[2][64 * KS_S];
    __shared__ __align__(16) unsigned Vs[2][32 * VS_S];
    __shared__ float Ms[2][64];

    int tid  = threadIdx.x;
    int w    = tid >> 5;
    int lane = tid & 31;
    int t4   = lane >> 2;
    int q    = lane & 3;

    int bh = blockIdx.y;
    int b  = bh >> 4;
    int h  = bh & 15;
    int q0 = blockIdx.x * 128;

    const unsigned* Qp = g_qb + (size_t)bh * SEQ * (HD/2) + (size_t)(q0 + w * 16) * (HD/2);
    const unsigned* Kp = g_kb + (size_t)bh * SEQ * (HD/2);
    const unsigned* Vp = g_vb + (size_t)bh * SEQ * (HD/2);
    const float* mrow  = mask + (size_t)b * SEQ;

    // Q A-fragments (already packed dim-pairs)
    unsigned aq[4][4];
    #pragma unroll
    for (int c = 0; c < 4; c++) {
        aq[c][0] = Qp[(size_t)(t4    ) * (HD/2) + c*8 + q    ];
        aq[c][1] = Qp[(size_t)(t4 + 8) * (HD/2) + c*8 + q    ];
        aq[c][2] = Qp[(size_t)(t4    ) * (HD/2) + c*8 + q + 4];
        aq[c][3] = Qp[(size_t)(t4 + 8) * (HD/2) + c*8 + q + 4];
    }

    // staging assignments (256 threads)
    int kr = tid & 63, kc = tid >> 6;     // K: key row, chunk (0..3): 2x16B per thread
    int vk = tid >> 3, vj = tid & 7;      // V: key-pair (0..31), dim-chunk (0..7)

    uint4 va, vb2;
    float mreg = 0.f;

    // K via cp.async: straight copy (layout matches gmem rows)
    auto LOADK = [&](int kt0, int st) {
        const unsigned* krow = Kp + (size_t)(kt0 + kr) * 32;
        cp16(&Ks[st][kr * KS_S + 4*kc     ], krow + 4*kc     );
        cp16(&Ks[st][kr * KS_S + 4*kc + 16], krow + 4*kc + 16);
        cp_commit();
    };
    auto LOADV = [&](int kt0) {
        va  = *(const uint4*)(Vp + (size_t)(kt0 + 2*vk    ) * 32 + 4*vj);
        vb2 = *(const uint4*)(Vp + (size_t)(kt0 + 2*vk + 1) * 32 + 4*vj);
        if (tid < 64) mreg = mrow[kt0 + tid] * LOG2E;
    };
    auto STOREV = [&](int st) {
        uint4 o0, o1;
        o0.x = __byte_perm(va.x, vb2.x, 0x5410);
        o0.y = __byte_perm(va.x, vb2.x, 0x7632);
        o0.z = __byte_perm(va.y, vb2.y, 0x5410);
        o0.w = __byte_perm(va.y, vb2.y, 0x7632);
        o1.x = __byte_perm(va.z, vb2.z, 0x5410);
        o1.y = __byte_perm(va.z, vb2.z, 0x7632);
        o1.z = __byte_perm(va.w, vb2.w, 0x5410);
        o1.w = __byte_perm(va.w, vb2.w, 0x7632);
        *(uint4*)&Vs[st][vk * VS_S + 8*vj    ] = o0;
        *(uint4*)&Vs[st][vk * VS_S + 8*vj + 4] = o1;
        if (tid < 64) Ms[st][tid] = mreg;
    };

    float mA = -1e30f, mB = -1e30f, lA = 0.f, lB = 0.f;
    float o[8][4];
    #pragma unroll
    for (int nt = 0; nt < 8; nt++)
        o[nt][0] = o[nt][1] = o[nt][2] = o[nt][3] = 0.f;

    LOADK(0, 0);
    LOADV(0);
    STOREV(0);
    cp_wait0();
    __syncthreads();

    int cur = 0;
    for (int t = 0; t < SEQ/64; t++) {
        if (t + 1 < SEQ/64) {
            LOADK((t + 1) * 64, cur ^ 1);
            LOADV((t + 1) * 64);
        }

        const unsigned* Kss = Ks[cur];
        const unsigned* Vss = Vs[cur];
        const float*    Mss = Ms[cur];

        // ---- QK^T ----
        float s[8][4];
        #pragma unroll
        for (int nt = 0; nt < 8; nt++)
            s[nt][0] = s[nt][1] = s[nt][2] = s[nt][3] = 0.f;

        #pragma unroll
        for (int c = 0; c < 4; c++) {
            #pragma unroll
            for (int nt = 0; nt < 8; nt++) {
                unsigned bb[2];
                bb[0] = Kss[(nt*8 + t4) * KS_S + c*8 + q    ];
                bb[1] = Kss[(nt*8 + t4) * KS_S + c*8 + 4 + q];
                mma_bf16(s[nt], aq[c], bb);
            }
        }

        // ---- scale + mask (base-2 domain) ----
        #pragma unroll
        for (int nt = 0; nt < 8; nt++) {
            float mk0 = Mss[nt*8 + 2*q];
            float mk1 = Mss[nt*8 + 2*q + 1];
            s[nt][0] = s[nt][0] * SC2 + mk0;
            s[nt][1] = s[nt][1] * SC2 + mk1;
            s[nt][2] = s[nt][2] * SC2 + mk0;
            s[nt][3] = s[nt][3] * SC2 + mk1;
        }

        // ---- online softmax, base 2 (rows rA=t4, rB=t4+8; quad reduce) ----
        float mxA = -1e30f, mxB = -1e30f;
        #pragma unroll
        for (int nt = 0; nt < 8; nt++) {
            mxA = fmaxf(mxA, fmaxf(s[nt][0], s[nt][1]));
            mxB = fmaxf(mxB, fmaxf(s[nt][2], s[nt][3]));
        }
        mxA = fmaxf(mxA, __shfl_xor_sync(0xffffffffu, mxA, 1));
        mxA = fmaxf(mxA, __shfl_xor_sync(0xffffffffu, mxA, 2));
        mxB = fmaxf(mxB, __shfl_xor_sync(0xffffffffu, mxB, 1));
        mxB = fmaxf(mxB, __shfl_xor_sync(0xffffffffu, mxB, 2));
        float mAn = fmaxf(mA, mxA), mBn = fmaxf(mB, mxB);
        float alA = exp2f(mA - mAn), alB = exp2f(mB - mBn);
        float sumA = 0.f, sumB = 0.f;
        #pragma unroll
        for (int nt = 0; nt < 8; nt++) {
            s[nt][0] = exp2f(s[nt][0] - mAn);
            s[nt][1] = exp2f(s[nt][1] - mAn);
            s[nt][2] = exp2f(s[nt][2] - mBn);
            s[nt][3] = exp2f(s[nt][3] - mBn);
            sumA += s[nt][0] + s[nt][1];
            sumB += s[nt][2] + s[nt][3];
        }
        sumA += __shfl_xor_sync(0xffffffffu, sumA, 1);
        sumA += __shfl_xor_sync(0xffffffffu, sumA, 2);
        sumB += __shfl_xor_sync(0xffffffffu, sumB, 1);
        sumB += __shfl_xor_sync(0xffffffffu, sumB, 2);
        lA = lA * alA + sumA;  mA = mAn;
        lB = lB * alB + sumB;  mB = mBn;
        #pragma unroll
        for (int nt = 0; nt < 8; nt++) {
            o[nt][0] *= alA; o[nt][1] *= alA;
            o[nt][2] *= alB; o[nt][3] *= alB;
        }

        // ---- PV: P D-fragments repack directly into A-fragments ----
        #pragma unroll
        for (int pk = 0; pk < 4; pk++) {
            unsigned pa[4];
            pa[0] = pack2(s[2*pk  ][0], s[2*pk  ][1]);
            pa[1] = pack2(s[2*pk  ][2], s[2*pk  ][3]);
            pa[2] = pack2(s[2*pk+1][0], s[2*pk+1][1]);
            pa[3] = pack2(s[2*pk+1][2], s[2*pk+1][3]);
            #pragma unroll
            for (int nt = 0; nt < 8; nt++) {
                unsigned bb[2];
                bb[0] = Vss[(pk*8 + q    ) * VS_S + nt*8 + t4];
                bb[1] = Vss[(pk*8 + q + 4) * VS_S + nt*8 + t4];
                mma_bf16(o[nt], pa, bb);
            }
        }

        if (t + 1 < SEQ/64) STOREV(cur ^ 1);
        cp_wait0();
        __syncthreads();
        cur ^= 1;
    }

    // ---- epilogue -> g_ctxb packed [B,S,H/2] ----
    float invA = 1.0f / lA, invB = 1.0f / lB;
    int srowA = q0 + w * 16 + t4;
    unsigned* crow  = g_ctxb + (size_t)(b * SEQ + srowA    ) * W2 + h * 32;
    unsigned* crow2 = g_ctxb + (size_t)(b * SEQ + srowA + 8) * W2 + h * 32;
    #pragma unroll
    for (int nt = 0; nt < 8; nt++) {
        crow [nt*4 + q] = pack2(o[nt][0] * invA, o[nt][1] * invA);
        crow2[nt*4 + q] = pack2(o[nt][2] * invB, o[nt][3] * invB);
    }
}

// ============================ launch ========================================
extern "C" void kernel_launch(void* const* d_in, const int* in_sizes, int n_in,
                              void* d_out, int out_size)
{
    const float* hs    = (const float*)d_in[0];
    const float* mask  = (const float*)d_in[1];
    const float* wq    = (const float*)d_in[2];
    const float* bq    = (const float*)d_in[3];
    const float* wk    = (const float*)d_in[4];
    const float* bk    = (const float*)d_in[5];
    const float* wv    = (const float*)d_in[6];
    const float* bv    = (const float*)d_in[7];
    const float* wo    = (const float*)d_in[8];
    const float* bo    = (const float*)d_in[9];
    const float* gamma = (const float*)d_in[10];
    const float* beta  = (const float*)d_in[11];
    float* out = (float*)d_out;

    conv_w<<<4096, 256>>>(wq, wk, wv, wo);
    ln_kernel<<<ROWS, 256>>>(hs, gamma, beta);
    qkv_gemm_t<<<dim3(HB/128, ROWS/128, 3), 256>>>(bq, bk, bv);
    attn_t<<<dim3(SEQ/128, BATCH*NH), 256>>>(mask);
    out_gemm_t<<<dim3(HB/128, ROWS/128), 256>>>(bo, hs, out);
}

// round 16
// speedup vs baseline: 1.9124x; 1.1300x over previous
#include <cuda_runtime.h>
#include <cuda_bf16.h>

// Problem dims
#define HB    1024
#define NH    16
#define HD    64
#define SEQ   2048
#define BATCH 2
#define ROWS  (BATCH*SEQ)     // 4096
#define EPS   1e-12f
#define W2    (HB/2)          // 512 packed u32 per hidden row
#define LOG2E 1.4426950408889634f

// -------------------- scratch (device globals; no runtime allocs) -----------
__device__ unsigned g_xnb [ROWS*W2];     // layernorm output, bf16 packed
__device__ unsigned g_wb  [4*HB*W2];     // wq,wk,wv,wo bf16 packed [mat][n][k2]
__device__ unsigned g_qb  [ROWS*W2];     // [B,NH,S,HD/2]
__device__ unsigned g_kb  [ROWS*W2];
__device__ unsigned g_vb  [ROWS*W2];
__device__ unsigned g_ctxb[ROWS*W2];     // [B,S,H/2]

// -------------------- bf16 helpers ------------------------------------------
__device__ __forceinline__ unsigned pack2(float a, float b) {
    unsigned r;
    asm("{ .reg .b16 lo, hi;\n\t"
        "cvt.rn.bf16.f32 lo, %1;\n\t"
        "cvt.rn.bf16.f32 hi, %2;\n\t"
        "mov.b32 %0, {lo, hi}; }"
        : "=r"(r) : "f"(a), "f"(b));
    return r;
}
// D += A(16x16) * B(16x8), bf16 in, f32 accum.
__device__ __forceinline__ void mma_bf16(float* d, const unsigned* a, const unsigned* b) {
    asm volatile(
        "mma.sync.aligned.m16n8k16.row.col.f32.bf16.bf16.f32 "
        "{%0,%1,%2,%3}, {%4,%5,%6,%7}, {%8,%9}, {%0,%1,%2,%3};"
        : "+f"(d[0]), "+f"(d[1]), "+f"(d[2]), "+f"(d[3])
        : "r"(a[0]), "r"(a[1]), "r"(a[2]), "r"(a[3]), "r"(b[0]), "r"(b[1]));
}
// cp.async 16B gmem -> smem
__device__ __forceinline__ void cp16(unsigned* smem_dst, const void* gsrc) {
    unsigned d = (unsigned)__cvta_generic_to_shared(smem_dst);
    asm volatile("cp.async.cg.shared.global [%0], [%1], 16;" :: "r"(d), "l"(gsrc));
}
__device__ __forceinline__ void cp_commit() {
    asm volatile("cp.async.commit_group;");
}
__device__ __forceinline__ void cp_wait0() {
    asm volatile("cp.async.wait_group 0;");
}

// ============================ LayerNorm (writes bf16 planes) ================
__global__ __launch_bounds__(256) void ln_kernel(
    const float* __restrict__ x,
    const float* __restrict__ gamma,
    const float* __restrict__ beta)
{
    int row = blockIdx.x;
    const float* xr = x + (size_t)row * HB;
    int tid = threadIdx.x;

    float4 v = *(const float4*)(xr + tid * 4);
    float s  = v.x + v.y + v.z + v.w;
    float ss = v.x*v.x + v.y*v.y + v.z*v.z + v.w*v.w;

    #pragma unroll
    for (int o = 16; o; o >>= 1) {
        s  += __shfl_xor_sync(0xffffffffu, s,  o);
        ss += __shfl_xor_sync(0xffffffffu, ss, o);
    }
    __shared__ float sh_s[8], sh_ss[8];
    int wid = tid >> 5, lid = tid & 31;
    if (lid == 0) { sh_s[wid] = s; sh_ss[wid] = ss; }
    __syncthreads();
    if (wid == 0) {
        float a = (lid < 8) ? sh_s[lid]  : 0.f;
        float b = (lid < 8) ? sh_ss[lid] : 0.f;
        #pragma unroll
        for (int o = 4; o; o >>= 1) {
            a += __shfl_xor_sync(0xffffffffu, a, o);
            b += __shfl_xor_sync(0xffffffffu, b, o);
        }
        if (lid == 0) { sh_s[0] = a; sh_ss[0] = b; }
    }
    __syncthreads();
    float mean = sh_s[0] * (1.0f / HB);
    float var  = sh_ss[0] * (1.0f / HB) - mean * mean;
    float rstd = rsqrtf(var + EPS);

    float4 g  = *(const float4*)(gamma + tid * 4);
    float4 be = *(const float4*)(beta + tid * 4);
    float o0 = (v.x - mean) * rstd * g.x + be.x;
    float o1 = (v.y - mean) * rstd * g.y + be.y;
    float o2 = (v.z - mean) * rstd * g.z + be.z;
    float o3 = (v.w - mean) * rstd * g.w + be.w;
    *(uint2*)(g_xnb + (size_t)row * W2 + tid * 2) =
        make_uint2(pack2(o0, o1), pack2(o2, o3));
}

// ============================ Weight conversion =============================
__global__ __launch_bounds__(256) void conv_w(
    const float* __restrict__ wq, const float* __restrict__ wk,
    const float* __restrict__ wv, const float* __restrict__ wo)
{
    int gid = blockIdx.x * 256 + threadIdx.x;
    int mat = gid >> 18;
    int off = gid & 262143;
    const float* src = (mat == 0 ? wq : mat == 1 ? wk : mat == 2 ? wv : wo)
                       + (size_t)off * 4;
    float4 v = *(const float4*)src;
    *(uint2*)(g_wb + (size_t)mat * HB * W2 + (size_t)off * 2) =
        make_uint2(pack2(v.x, v.y), pack2(v.z, v.w));
}

// ====================== bf16 GEMM mainloop (cp.async 2-stage) ===============
// C[128,128]/block, BK=32, 256 thr = 8 warps, warp tile 64x32.
// Smem row-major [row][k2], stride 20 u32 (20*t4 mod 32 distinct -> frag LDS
// conflict-free). Warps 0-3 side A, 4-7 side B; 4 cp16 per thread per stage.
#define RS    20              // row stride in u32
#define PLN   (128*RS)        // one plane (A or B), one stage = 2560 u32
#define STAG  (2*PLN)         // A+B planes, one stage

__device__ __forceinline__ void gemm_mainloop(
    const unsigned* __restrict__ Ag,
    const unsigned* __restrict__ Bg,
    unsigned* Sh,                       // [2][2][PLN] = 2 stages x (A,B)
    float (*acc)[4][4])
{
    int tid  = threadIdx.x;
    int side = tid >> 7;
    int row  = tid & 127;
    int lane = tid & 31, w = tid >> 5;
    int t4 = lane >> 2, q = lane & 3;
    int wm = (w >> 2) * 64, wn = (w & 3) * 32;

    const unsigned* grow = (side ? Bg : Ag) + (size_t)row * W2;
    unsigned* srow0 = Sh + side * PLN + row * RS;

    // prologue: stage 0
    {
        cp16(srow0 +  0, grow +  0);
        cp16(srow0 +  4, grow +  4);
        cp16(srow0 +  8, grow +  8);
        cp16(srow0 + 12, grow + 12);
        cp_commit();
    }

    int cur = 0;
    for (int t = 0; t < HB/32; t++) {
        cp_wait0();
        __syncthreads();
        if (t + 1 < HB/32) {
            unsigned* sd = srow0 + (cur ^ 1) * STAG;
            const unsigned* gs = grow + (t + 1) * 16;
            cp16(sd +  0, gs +  0);
            cp16(sd +  4, gs +  4);
            cp16(sd +  8, gs +  8);
            cp16(sd + 12, gs + 12);
            cp_commit();
        }
        const unsigned* Ahs = Sh + cur * STAG;
        const unsigned* Bhs = Ahs + PLN;
        #pragma unroll
        for (int s = 0; s < 2; s++) {
            int kb = s * 8;
            unsigned ah[4][4], bh[4][2];
            #pragma unroll
            for (int mt = 0; mt < 4; mt++) {
                int r = wm + mt*16 + t4;
                ah[mt][0] = Ahs[ r      * RS + kb + q    ];
                ah[mt][1] = Ahs[(r + 8) * RS + kb + q    ];
                ah[mt][2] = Ahs[ r      * RS + kb + q + 4];
                ah[mt][3] = Ahs[(r + 8) * RS + kb + q + 4];
            }
            #pragma unroll
            for (int nt = 0; nt < 4; nt++) {
                int c = wn + nt*8 + t4;
                bh[nt][0] = Bhs[c * RS + kb + q    ];
                bh[nt][1] = Bhs[c * RS + kb + q + 4];
            }
            #pragma unroll
            for (int mt = 0; mt < 4; mt++)
                #pragma unroll
                for (int nt = 0; nt < 4; nt++)
                    mma_bf16(acc[mt][nt], ah[mt], bh[nt]);
        }
        cur ^= 1;
    }
}

// ---- QKV projections: write packed bf16, scattered to [B,NH,S,HD/2] --------
__global__ __launch_bounds__(256, 2) void qkv_gemm_t(
    const float* __restrict__ bq, const float* __restrict__ bk,
    const float* __restrict__ bv)
{
    int z = blockIdx.z;
    const float* bias = (z == 0) ? bq : (z == 1) ? bk : bv;
    unsigned* O = (z == 0) ? g_qb : (z == 1) ? g_kb : g_vb;

    __shared__ __align__(16) unsigned Sh[2*STAG];

    const unsigned* Ag = g_xnb + (size_t)(blockIdx.y * 128) * W2;
    const unsigned* Bg = g_wb + (size_t)z * HB * W2 + (size_t)(blockIdx.x * 128) * W2;

    float acc[4][4][4];
    #pragma unroll
    for (int mt = 0; mt < 4; mt++)
        #pragma unroll
        for (int nt = 0; nt < 4; nt++)
            acc[mt][nt][0] = acc[mt][nt][1] = acc[mt][nt][2] = acc[mt][nt][3] = 0.f;

    gemm_mainloop(Ag, Bg, Sh, acc);

    int tid = threadIdx.x;
    int lane = tid & 31, w = tid >> 5;
    int t4 = lane >> 2, q = lane & 3;
    int wm = (w >> 2) * 64, wn = (w & 3) * 32;

    #pragma unroll
    for (int nt = 0; nt < 4; nt++) {
        int col = blockIdx.x * 128 + wn + nt*8 + 2*q;
        int h   = col >> 6;
        int dp  = (col & 63) >> 1;
        float b0 = bias[col], b1 = bias[col + 1];
        #pragma unroll
        for (int mt = 0; mt < 4; mt++) {
            int m  = blockIdx.y * 128 + wm + mt*16 + t4;
            int b_ = m >> 11;
            int s_ = m & 2047;
            unsigned* dst = O + ((size_t)(b_ * NH + h) * SEQ + s_) * (HD/2) + dp;
            dst[0]          = pack2(acc[mt][nt][0] + b0, acc[mt][nt][1] + b1);
            dst[8 * (HD/2)] = pack2(acc[mt][nt][2] + b0, acc[mt][nt][3] + b1);
        }
    }
}

// ---- Output projection + residual (f32 out) --------------------------------
__global__ __launch_bounds__(256, 2) void out_gemm_t(
    const float* __restrict__ bo,
    const float* __restrict__ hs, float* __restrict__ out)
{
    __shared__ __align__(16) unsigned Sh[2*STAG];

    const unsigned* Ag = g_ctxb + (size_t)(blockIdx.y * 128) * W2;
    const unsigned* Bg = g_wb + (size_t)3 * HB * W2 + (size_t)(blockIdx.x * 128) * W2;

    float acc[4][4][4];
    #pragma unroll
    for (int mt = 0; mt < 4; mt++)
        #pragma unroll
        for (int nt = 0; nt < 4; nt++)
            acc[mt][nt][0] = acc[mt][nt][1] = acc[mt][nt][2] = acc[mt][nt][3] = 0.f;

    gemm_mainloop(Ag, Bg, Sh, acc);

    int tid = threadIdx.x;
    int lane = tid & 31, w = tid >> 5;
    int t4 = lane >> 2, q = lane & 3;
    int wm = (w >> 2) * 64, wn = (w & 3) * 32;

    #pragma unroll
    for (int nt = 0; nt < 4; nt++) {
        int col = blockIdx.x * 128 + wn + nt*8 + 2*q;
        float b0 = bo[col], b1 = bo[col + 1];
        #pragma unroll
        for (int mt = 0; mt < 4; mt++) {
            int m = blockIdx.y * 128 + wm + mt*16 + t4;
            const float* hr = hs + (size_t)m * HB + col;
            float* dst = out + (size_t)m * HB + col;
            float2 r0 = *(const float2*)hr;
            *(float2*)dst = make_float2(acc[mt][nt][0] + b0 + r0.x,
                                        acc[mt][nt][1] + b1 + r0.y);
            const float* hr2 = hr + 8 * HB;
            float* dst2 = dst + 8 * HB;
            float2 r1 = *(const float2*)hr2;
            *(float2*)dst2 = make_float2(acc[mt][nt][2] + b0 + r1.x,
                                         acc[mt][nt][3] + b1 + r1.y);
        }
    }
}

// ============================ Flash attention (unchanged from R15) ==========
// 256 threads / 8 warps, 128 queries per CTA, 2 CTAs/SM.
// K staged by cp.async; V staged via regs + byte_perm repack.
// Double-buffered, base-2 softmax.
#define KS_S 36   // u32 stride, Ks rows = keys, cols = dim-pairs
#define VS_S 72   // u32 stride, Vs rows = key-pairs, cols = dims
#define SC2  (0.125f * LOG2E)

__global__ __launch_bounds__(256, 2) void attn_t(const float* __restrict__ mask)
{
    __shared__ __align__(16) unsigned Ks[2][64 * KS_S];
    __shared__ __align__(16) unsigned Vs[2][32 * VS_S];
    __shared__ float Ms[2][64];

    int tid  = threadIdx.x;
    int w    = tid >> 5;
    int lane = tid & 31;
    int t4   = lane >> 2;
    int q    = lane & 3;

    int bh = blockIdx.y;
    int b  = bh >> 4;
    int h  = bh & 15;
    int q0 = blockIdx.x * 128;

    const unsigned* Qp = g_qb + (size_t)bh * SEQ * (HD/2) + (size_t)(q0 + w * 16) * (HD/2);
    const unsigned* Kp = g_kb + (size_t)bh * SEQ * (HD/2);
    const unsigned* Vp = g_vb + (size_t)bh * SEQ * (HD/2);
    const float* mrow  = mask + (size_t)b * SEQ;

    // Q A-fragments (already packed dim-pairs)
    unsigned aq[4][4];
    #pragma unroll
    for (int c = 0; c < 4; c++) {
        aq[c][0] = Qp[(size_t)(t4    ) * (HD/2) + c*8 + q    ];
        aq[c][1] = Qp[(size_t)(t4 + 8) * (HD/2) + c*8 + q    ];
        aq[c][2] = Qp[(size_t)(t4    ) * (HD/2) + c*8 + q + 4];
        aq[c][3] = Qp[(size_t)(t4 + 8) * (HD/2) + c*8 + q + 4];
    }

    // staging assignments (256 threads)
    int kr = tid & 63, kc = tid >> 6;     // K: key row, chunk (0..3): 2x16B per thread
    int vk = tid >> 3, vj = tid & 7;      // V: key-pair (0..31), dim-chunk (0..7)

    uint4 va, vb2;
    float mreg = 0.f;

    auto LOADK = [&](int kt0, int st) {
        const unsigned* krow = Kp + (size_t)(kt0 + kr) * 32;
        cp16(&Ks[st][kr * KS_S + 4*kc     ], krow + 4*kc     );
        cp16(&Ks[st][kr * KS_S + 4*kc + 16], krow + 4*kc + 16);
        cp_commit();
    };
    auto LOADV = [&](int kt0) {
        va  = *(const uint4*)(Vp + (size_t)(kt0 + 2*vk    ) * 32 + 4*vj);
        vb2 = *(const uint4*)(Vp + (size_t)(kt0 + 2*vk + 1) * 32 + 4*vj);
        if (tid < 64) mreg = mrow[kt0 + tid] * LOG2E;
    };
    auto STOREV = [&](int st) {
        uint4 o0, o1;
        o0.x = __byte_perm(va.x, vb2.x, 0x5410);
        o0.y = __byte_perm(va.x, vb2.x, 0x7632);
        o0.z = __byte_perm(va.y, vb2.y, 0x5410);
        o0.w = __byte_perm(va.y, vb2.y, 0x7632);
        o1.x = __byte_perm(va.z, vb2.z, 0x5410);
        o1.y = __byte_perm(va.z, vb2.z, 0x7632);
        o1.z = __byte_perm(va.w, vb2.w, 0x5410);
        o1.w = __byte_perm(va.w, vb2.w, 0x7632);
        *(uint4*)&Vs[st][vk * VS_S + 8*vj    ] = o0;
        *(uint4*)&Vs[st][vk * VS_S + 8*vj + 4] = o1;
        if (tid < 64) Ms[st][tid] = mreg;
    };

    float mA = -1e30f, mB = -1e30f, lA = 0.f, lB = 0.f;
    float o[8][4];
    #pragma unroll
    for (int nt = 0; nt < 8; nt++)
        o[nt][0] = o[nt][1] = o[nt][2] = o[nt][3] = 0.f;

    LOADK(0, 0);
    LOADV(0);
    STOREV(0);
    cp_wait0();
    __syncthreads();

    int cur = 0;
    for (int t = 0; t < SEQ/64; t++) {
        if (t + 1 < SEQ/64) {
            LOADK((t + 1) * 64, cur ^ 1);
            LOADV((t + 1) * 64);
        }

        const unsigned* Kss = Ks[cur];
        const unsigned* Vss = Vs[cur];
        const float*    Mss = Ms[cur];

        // ---- QK^T ----
        float s[8][4];
        #pragma unroll
        for (int nt = 0; nt < 8; nt++)
            s[nt][0] = s[nt][1] = s[nt][2] = s[nt][3] = 0.f;

        #pragma unroll
        for (int c = 0; c < 4; c++) {
            #pragma unroll
            for (int nt = 0; nt < 8; nt++) {
                unsigned bb[2];
                bb[0] = Kss[(nt*8 + t4) * KS_S + c*8 + q    ];
                bb[1] = Kss[(nt*8 + t4) * KS_S + c*8 + 4 + q];
                mma_bf16(s[nt], aq[c], bb);
            }
        }

        // ---- scale + mask (base-2 domain) ----
        #pragma unroll
        for (int nt = 0; nt < 8; nt++) {
            float mk0 = Mss[nt*8 + 2*q];
            float mk1 = Mss[nt*8 + 2*q + 1];
            s[nt][0] = s[nt][0] * SC2 + mk0;
            s[nt][1] = s[nt][1] * SC2 + mk1;
            s[nt][2] = s[nt][2] * SC2 + mk0;
            s[nt][3] = s[nt][3] * SC2 + mk1;
        }

        // ---- online softmax, base 2 (rows rA=t4, rB=t4+8; quad reduce) ----
        float mxA = -1e30f, mxB = -1e30f;
        #pragma unroll
        for (int nt = 0; nt < 8; nt++) {
            mxA = fmaxf(mxA, fmaxf(s[nt][0], s[nt][1]));
            mxB = fmaxf(mxB, fmaxf(s[nt][2], s[nt][3]));
        }
        mxA = fmaxf(mxA, __shfl_xor_sync(0xffffffffu, mxA, 1));
        mxA = fmaxf(mxA, __shfl_xor_sync(0xffffffffu, mxA, 2));
        mxB = fmaxf(mxB, __shfl_xor_sync(0xffffffffu, mxB, 1));
        mxB = fmaxf(mxB, __shfl_xor_sync(0xffffffffu, mxB, 2));
        float mAn = fmaxf(mA, mxA), mBn = fmaxf(mB, mxB);
        float alA = exp2f(mA - mAn), alB = exp2f(mB - mBn);
        float sumA = 0.f, sumB = 0.f;
        #pragma unroll
        for (int nt = 0; nt < 8; nt++) {
            s[nt][0] = exp2f(s[nt][0] - mAn);
            s[nt][1] = exp2f(s[nt][1] - mAn);
            s[nt][2] = exp2f(s[nt][2] - mBn);
            s[nt][3] = exp2f(s[nt][3] - mBn);
            sumA += s[nt][0] + s[nt][1];
            sumB += s[nt][2] + s[nt][3];
        }
        sumA += __shfl_xor_sync(0xffffffffu, sumA, 1);
        sumA += __shfl_xor_sync(0xffffffffu, sumA, 2);
        sumB += __shfl_xor_sync(0xffffffffu, sumB, 1);
        sumB += __shfl_xor_sync(0xffffffffu, sumB, 2);
        lA = lA * alA + sumA;  mA = mAn;
        lB = lB * alB + sumB;  mB = mBn;
        #pragma unroll
        for (int nt = 0; nt < 8; nt++) {
            o[nt][0] *= alA; o[nt][1] *= alA;
            o[nt][2] *= alB; o[nt][3] *= alB;
        }

        // ---- PV: P D-fragments repack directly into A-fragments ----
        #pragma unroll
        for (int pk = 0; pk < 4; pk++) {
            unsigned pa[4];
            pa[0] = pack2(s[2*pk  ][0], s[2*pk  ][1]);
            pa[1] = pack2(s[2*pk  ][2], s[2*pk  ][3]);
            pa[2] = pack2(s[2*pk+1][0], s[2*pk+1][1]);
            pa[3] = pack2(s[2*pk+1][2], s[2*pk+1][3]);
            #pragma unroll
            for (int nt = 0; nt < 8; nt++) {
                unsigned bb[2];
                bb[0] = Vss[(pk*8 + q    ) * VS_S + nt*8 + t4];
                bb[1] = Vss[(pk*8 + q + 4) * VS_S + nt*8 + t4];
                mma_bf16(o[nt], pa, bb);
            }
        }

        if (t + 1 < SEQ/64) STOREV(cur ^ 1);
        cp_wait0();
        __syncthreads();
        cur ^= 1;
    }

    // ---- epilogue -> g_ctxb packed [B,S,H/2] ----
    float invA = 1.0f / lA, invB = 1.0f / lB;
    int srowA = q0 + w * 16 + t4;
    unsigned* crow  = g_ctxb + (size_t)(b * SEQ + srowA    ) * W2 + h * 32;
    unsigned* crow2 = g_ctxb + (size_t)(b * SEQ + srowA + 8) * W2 + h * 32;
    #pragma unroll
    for (int nt = 0; nt < 8; nt++) {
        crow [nt*4 + q] = pack2(o[nt][0] * invA, o[nt][1] * invA);
        crow2[nt*4 + q] = pack2(o[nt][2] * invB, o[nt][3] * invB);
    }
}

// ============================ launch ========================================
extern "C" void kernel_launch(void* const* d_in, const int* in_sizes, int n_in,
                              void* d_out, int out_size)
{
    const float* hs    = (const float*)d_in[0];
    const float* mask  = (const float*)d_in[1];
    const float* wq    = (const float*)d_in[2];
    const float* bq    = (const float*)d_in[3];
    const float* wk    = (const float*)d_in[4];
    const float* bk    = (const float*)d_in[5];
    const float* wv    = (const float*)d_in[6];
    const float* bv    = (const float*)d_in[7];
    const float* wo    = (const float*)d_in[8];
    const float* bo    = (const float*)d_in[9];
    const float* gamma = (const float*)d_in[10];
    const float* beta  = (const float*)d_in[11];
    float* out = (float*)d_out;

    conv_w<<<4096, 256>>>(wq, wk, wv, wo);
    ln_kernel<<<ROWS, 256>>>(hs, gamma, beta);
    qkv_gemm_t<<<dim3(HB/128, ROWS/128, 3), 256>>>(bq, bk, bv);
    attn_t<<<dim3(SEQ/128, BATCH*NH), 256>>>(mask);
    out_gemm_t<<<dim3(HB/128, ROWS/128), 256>>>(bo, hs, out);
}